// round 9
// baseline (speedup 1.0000x reference)
#include <cuda_runtime.h>
#include <cuda_bf16.h>
#include <cstdint>

#define N_NODES 50000
#define N_EDGES 800000
#define DIM     64
#define NLAYERS 3
#define N_CHUNKS (N_EDGES / 16)          // 50000 16-edge chunks

// A/B row strides in bf16 elems (64 data + 8 pad -> conflict-free LDSM)
#define RA 72
#define RB 72
#define OFF_A_HI 0
#define OFF_A_LO (128 * RA)
#define OFF_B_HI (2 * 128 * RA)
#define OFF_B_LO (2 * 128 * RA + 64 * RB)
#define SMEM_ELEMS (2 * 128 * RA + 2 * 64 * RB)
#define SMEM_BYTES (SMEM_ELEMS * 2)

#define SCATTER_GRID 1184                // 8 CTAs/SM on 148 SMs, single wave

// Scratch (no cudaMalloc allowed).
__device__ float g_bufA[N_NODES * DIM];
__device__ float g_bufB[N_NODES * DIM];
__device__ float g_agg [N_NODES * DIM];

// ---------------------------------------------------------------------------
// Zero agg (once, before layer-1 scatter; later layers zeroed inside GEMM)
// ---------------------------------------------------------------------------
__global__ void zero_kernel(float4* __restrict__ p, int n4) {
    int i = blockIdx.x * blockDim.x + threadIdx.x;
    if (i < n4) p[i] = make_float4(0.f, 0.f, 0.f, 0.f);
}

// ---------------------------------------------------------------------------
// Persistent scatter via TMA bulk-reduce: agg[dst] += ew * h[src].
// Single-wave grid; fires griddepcontrol.launch_dependents immediately so
// the PDL GEMM's scatter-independent stage overlaps this L2-bound kernel.
// Each warp loops over 16-edge chunks; SMEM buffer drained (wait_group 0)
// before each re-stage.
// ---------------------------------------------------------------------------
__global__ __launch_bounds__(128) void scatter_tma_kernel(
    const float4* __restrict__ h,
    const int*    __restrict__ src,
    const int*    __restrict__ dst,
    const float*  __restrict__ ew,
    float*        __restrict__ agg)
{
    __shared__ float4 buf[4][16][16];   // [warp][edge][lane16] = 16KB

    // Let PDL dependents (GEMM stage-0) launch right away.
    asm volatile("griddepcontrol.launch_dependents;" ::: "memory");

    const int warp = threadIdx.x >> 5;
    const int lane = threadIdx.x & 31;
    const int sub  = lane >> 4;
    const int l16  = lane & 15;

    const int warpsTotal = SCATTER_GRID * 4;
    const int wg = blockIdx.x * 4 + warp;

    for (int chunk = wg; chunk < N_CHUNKS; chunk += warpsTotal) {
        // Drain previous chunk's bulk reads of this warp's buffer.
        if (lane < 16)
            asm volatile("cp.async.bulk.wait_group 0;" ::: "memory");
        __syncwarp();

        const long eBase = (long)chunk * 16;

        int   myS = 0, myD = 0;
        float myW = 0.f;
        if (lane < 16) {
            myS = __ldg(src + eBase + lane);
            myD = __ldg(dst + eBase + lane);
            myW = __ldg(ew  + eBase + lane);
        }

        #pragma unroll
        for (int it = 0; it < 8; it++) {
            int   k = it * 2 + sub;
            int   s = __shfl_sync(0xffffffffu, myS, k);
            float w = __shfl_sync(0xffffffffu, myW, k);
            float4 v = __ldg(h + (size_t)s * 16 + l16);
            v.x *= w; v.y *= w; v.z *= w; v.w *= w;
            buf[warp][k][l16] = v;
        }
        __syncwarp();
        asm volatile("fence.proxy.async.shared::cta;" ::: "memory");

        if (lane < 16) {
            uint32_t sp = (uint32_t)__cvta_generic_to_shared(&buf[warp][lane][0]);
            float* gp = agg + (size_t)myD * 64;
            asm volatile(
                "cp.reduce.async.bulk.global.shared::cta.bulk_group.add.f32 "
                "[%0], [%1], %2;"
                :: "l"(gp), "r"(sp), "n"(256) : "memory");
            asm volatile("cp.async.bulk.commit_group;" ::: "memory");
        }
    }

    if (lane < 16)
        asm volatile("cp.async.bulk.wait_group 0;" ::: "memory");
}

// ---------------------------------------------------------------------------
// Tensor-core dual GEMM, bf16-split, fp32 accum. PDL-aware:
// stage 0 (H @ Wroot) runs pre-sync (overlaps the scatter);
// cudaGridDependencySynchronize() gates stage 1 (AGG @ Wrel).
// ---------------------------------------------------------------------------
__device__ __forceinline__ void ldsm_x4(uint32_t& r0, uint32_t& r1,
                                        uint32_t& r2, uint32_t& r3,
                                        uint32_t addr) {
    asm volatile("ldmatrix.sync.aligned.m8n8.x4.shared.b16 {%0,%1,%2,%3}, [%4];"
                 : "=r"(r0), "=r"(r1), "=r"(r2), "=r"(r3) : "r"(addr));
}

__device__ __forceinline__ void mma_bf16(float* d, const uint32_t* a,
                                         uint32_t b0, uint32_t b1) {
    asm volatile(
        "mma.sync.aligned.m16n8k16.row.col.f32.bf16.bf16.f32 "
        "{%0,%1,%2,%3}, {%4,%5,%6,%7}, {%8,%9}, {%0,%1,%2,%3};"
        : "+f"(d[0]), "+f"(d[1]), "+f"(d[2]), "+f"(d[3])
        : "r"(a[0]), "r"(a[1]), "r"(a[2]), "r"(a[3]), "r"(b0), "r"(b1));
}

__device__ __forceinline__ void split2(float a, float b,
                                       __nv_bfloat162& h, __nv_bfloat162& l) {
    __nv_bfloat16 ha = __float2bfloat16_rn(a);
    __nv_bfloat16 hb = __float2bfloat16_rn(b);
    float la = a - __bfloat162float(ha);
    float lb = b - __bfloat162float(hb);
    h = __halves2bfloat162(ha, hb);
    l = __halves2bfloat162(__float2bfloat16_rn(la), __float2bfloat16_rn(lb));
}

__global__ __launch_bounds__(256) void gemm_tc_kernel(
    const float* __restrict__ H,
    float*                    AGG,     // no restrict: loaded then zeroed
    const float* __restrict__ Wroot,   // [64][64]
    const float* __restrict__ Wrel,    // [64][64]
    const float* __restrict__ bias,    // [64]
    float*       __restrict__ out,
    int doTanh, int doZero)
{
    extern __shared__ __nv_bfloat16 sm[];
    uint32_t sbase;
    asm("{.reg .u64 t; cvta.to.shared.u64 t, %1; cvt.u32.u64 %0, t;}"
        : "=r"(sbase) : "l"(sm));

    const int tid     = threadIdx.x;
    const int lane    = tid & 31;
    const int warp    = tid >> 5;
    const int wm      = warp >> 1;
    const int wn      = warp & 1;
    const int rowBase = blockIdx.x * 128;

    float acc[2][4][4];
    #pragma unroll
    for (int mi = 0; mi < 2; mi++)
        #pragma unroll
        for (int ni = 0; ni < 4; ni++)
            #pragma unroll
            for (int k = 0; k < 4; k++) acc[mi][ni][k] = 0.f;

    const int m0 = wm * 32;
    const int n0 = wn * 32;
    const int aRow  = m0 + (lane & 15);
    const int aColB = (lane >> 4) * 8;
    const int bRow  = n0 + (lane & 7) + ((lane >> 4) * 8);
    const int bColB = ((lane >> 3) & 1) * 8;

    #pragma unroll 1
    for (int s = 0; s < 2; s++) {
        __syncthreads();

        // Gate only the scatter-dependent stage.
        if (s == 1) cudaGridDependencySynchronize();

        const float* S = s ? (const float*)AGG : H;
        #pragma unroll
        for (int i = 0; i < 8; i++) {
            int q   = tid + i * 256;
            int row = q >> 4;
            int c4  = (q & 15) * 4;
            int gr  = rowBase + row;
            float4 v = make_float4(0.f, 0.f, 0.f, 0.f);
            if (gr < N_NODES) v = *(const float4*)(S + (size_t)gr * 64 + c4);
            __nv_bfloat162 h0, l0, h1, l1;
            split2(v.x, v.y, h0, l0);
            split2(v.z, v.w, h1, l1);
            int base = row * RA + c4;
            *(__nv_bfloat162*)&sm[OFF_A_HI + base]     = h0;
            *(__nv_bfloat162*)&sm[OFF_A_HI + base + 2] = h1;
            *(__nv_bfloat162*)&sm[OFF_A_LO + base]     = l0;
            *(__nv_bfloat162*)&sm[OFF_A_LO + base + 2] = l1;
            if (s == 1 && doZero && gr < N_NODES)
                *(float4*)(AGG + (size_t)gr * 64 + c4) =
                    make_float4(0.f, 0.f, 0.f, 0.f);
        }

        const float* Wm = s ? Wrel : Wroot;
        #pragma unroll
        for (int i = 0; i < 16; i++) {
            int q = tid + i * 256;
            int k = q >> 6;
            int n = q & 63;
            float w = __ldg(Wm + k * 64 + n);
            __nv_bfloat16 hw = __float2bfloat16_rn(w);
            float lw = w - __bfloat162float(hw);
            sm[OFF_B_HI + n * RB + k] = hw;
            sm[OFF_B_LO + n * RB + k] = __float2bfloat16_rn(lw);
        }
        __syncthreads();

        const int aOffC[3] = { OFF_A_HI, OFF_A_HI, OFF_A_LO };
        const int bOffC[3] = { OFF_B_HI, OFF_B_LO, OFF_B_HI };
        #pragma unroll
        for (int c = 0; c < 3; c++) {
            uint32_t aBase = sbase + (uint32_t)(aOffC[c] + aRow * RA + aColB) * 2;
            uint32_t bBase = sbase + (uint32_t)(bOffC[c] + bRow * RB + bColB) * 2;
            #pragma unroll
            for (int ks = 0; ks < 4; ks++) {
                uint32_t a[2][4], b[2][4];
                #pragma unroll
                for (int mi = 0; mi < 2; mi++)
                    ldsm_x4(a[mi][0], a[mi][1], a[mi][2], a[mi][3],
                            aBase + (uint32_t)(mi * 16 * RA + ks * 16) * 2);
                #pragma unroll
                for (int nb = 0; nb < 2; nb++)
                    ldsm_x4(b[nb][0], b[nb][1], b[nb][2], b[nb][3],
                            bBase + (uint32_t)(nb * 16 * RB + ks * 16) * 2);
                #pragma unroll
                for (int mi = 0; mi < 2; mi++)
                    #pragma unroll
                    for (int ni = 0; ni < 4; ni++)
                        mma_bf16(acc[mi][ni], a[mi],
                                 b[ni >> 1][(ni & 1) * 2],
                                 b[ni >> 1][(ni & 1) * 2 + 1]);
            }
        }
    }

    #pragma unroll
    for (int mi = 0; mi < 2; mi++) {
        #pragma unroll
        for (int ni = 0; ni < 4; ni++) {
            int col = n0 + ni * 8 + (lane & 3) * 2;
            float b0 = __ldg(bias + col);
            float b1 = __ldg(bias + col + 1);
            int r0 = rowBase + m0 + mi * 16 + (lane >> 2);
            #pragma unroll
            for (int h = 0; h < 2; h++) {
                int r = r0 + h * 8;
                if (r >= N_NODES) continue;
                float v0 = acc[mi][ni][h * 2]     + b0;
                float v1 = acc[mi][ni][h * 2 + 1] + b1;
                if (doTanh) {
                    asm("tanh.approx.f32 %0, %0;" : "+f"(v0));
                    asm("tanh.approx.f32 %0, %0;" : "+f"(v1));
                }
                *(float2*)(out + (size_t)r * 64 + col) = make_float2(v0, v1);
            }
        }
    }
}

// ---------------------------------------------------------------------------
// Launcher
// ---------------------------------------------------------------------------
extern "C" void kernel_launch(void* const* d_in, const int* in_sizes, int n_in,
                              void* d_out, int out_size)
{
    const float* x      = (const float*)d_in[0];
    const int*   eidx   = (const int*)  d_in[1];
    const float* ew     = (const float*)d_in[2];
    const float* W_rel  = (const float*)d_in[3];
    const float* b_rel  = (const float*)d_in[4];
    const float* W_root = (const float*)d_in[5];
    float* out = (float*)d_out;

    const int* src = eidx;
    const int* dst = eidx + N_EDGES;

    float *pA, *pB, *pAgg;
    cudaGetSymbolAddress((void**)&pA,   g_bufA);
    cudaGetSymbolAddress((void**)&pB,   g_bufB);
    cudaGetSymbolAddress((void**)&pAgg, g_agg);

    static bool attrSet = false;
    if (!attrSet) {
        cudaFuncSetAttribute(gemm_tc_kernel,
                             cudaFuncAttributeMaxDynamicSharedMemorySize,
                             SMEM_BYTES);
        attrSet = true;
    }

    const int n4 = N_NODES * (DIM / 4);
    const int zeroBlocks = (n4 + 255) / 256;
    const int gemmBlocks = (N_NODES + 127) / 128;   // 391

    zero_kernel<<<zeroBlocks, 256>>>((float4*)pAgg, n4);

    const float* hprev = x;
    for (int layer = 0; layer < NLAYERS; layer++) {
        float* hnext = (layer == NLAYERS - 1) ? out : ((layer == 0) ? pA : pB);

        scatter_tma_kernel<<<SCATTER_GRID, 128>>>(
            (const float4*)hprev, src, dst, ew, pAgg);

        // GEMM as PDL secondary: stage 0 overlaps the scatter.
        {
            cudaLaunchConfig_t cfg = {};
            cfg.gridDim  = dim3(gemmBlocks);
            cfg.blockDim = dim3(256);
            cfg.dynamicSmemBytes = SMEM_BYTES;
            cfg.stream = 0;
            cudaLaunchAttribute at[1];
            at[0].id = cudaLaunchAttributeProgrammaticStreamSerialization;
            at[0].val.programmaticStreamSerializationAllowed = 1;
            cfg.attrs = at;
            cfg.numAttrs = 1;

            const float* Wr = W_root + (size_t)layer * DIM * DIM;
            const float* We = W_rel  + (size_t)layer * DIM * DIM;
            const float* bs = b_rel  + (size_t)layer * DIM;
            int doTanh = (layer == NLAYERS - 1) ? 1 : 0;
            int doZero = (layer == NLAYERS - 1) ? 0 : 1;
            cudaLaunchKernelEx(&cfg, gemm_tc_kernel,
                               hprev, pAgg, Wr, We, bs, hnext, doTanh, doZero);
        }

        hprev = hnext;
    }
}

// round 10
// speedup vs baseline: 1.0556x; 1.0556x over previous
#include <cuda_runtime.h>
#include <cuda_bf16.h>
#include <cstdint>

#define N_NODES 50000
#define N_EDGES 800000
#define DIM     64
#define NLAYERS 3

// A/B row strides in bf16 elems (64 data + 8 pad -> conflict-free LDSM)
#define RA 72
#define RB 72
#define OFF_A_HI 0
#define OFF_A_LO (128 * RA)
#define OFF_B_HI (2 * 128 * RA)
#define OFF_B_LO (2 * 128 * RA + 64 * RB)
#define SMEM_ELEMS (2 * 128 * RA + 2 * 64 * RB)
#define SMEM_BYTES (SMEM_ELEMS * 2)

// Scratch (no cudaMalloc allowed).
__device__ float g_bufA[N_NODES * DIM];
__device__ float g_bufB[N_NODES * DIM];
__device__ float g_agg [N_NODES * DIM];
__device__ int   g_dummy;

// ---------------------------------------------------------------------------
// Dummy launch: shifts ncu's -s5 -c1 window so launch #6 is a GEMM.
// ---------------------------------------------------------------------------
__global__ void dummy_kernel() {
    if (threadIdx.x == 0 && blockIdx.x == 0) g_dummy = 0;
}

// ---------------------------------------------------------------------------
// Zero agg (once, before layer-1 scatter; later layers zeroed inside GEMM)
// ---------------------------------------------------------------------------
__global__ void zero_kernel(float4* __restrict__ p, int n4) {
    int i = blockIdx.x * blockDim.x + threadIdx.x;
    if (i < n4) p[i] = make_float4(0.f, 0.f, 0.f, 0.f);
}

// ---------------------------------------------------------------------------
// Scatter via TMA bulk-reduce (R6 version — fully pipelined, at L2 floor).
// ---------------------------------------------------------------------------
__global__ __launch_bounds__(128) void scatter_tma_kernel(
    const float4* __restrict__ h,
    const int*    __restrict__ src,
    const int*    __restrict__ dst,
    const float*  __restrict__ ew,
    float*        __restrict__ agg)
{
    __shared__ float4 buf[4][16][16];   // [warp][edge][lane16] = 16KB

    const int warp = threadIdx.x >> 5;
    const int lane = threadIdx.x & 31;
    const int sub  = lane >> 4;
    const int l16  = lane & 15;

    const long eBase = ((long)blockIdx.x * 4 + warp) * 16;

    int   myS = 0, myD = 0;
    float myW = 0.f;
    if (lane < 16) {
        myS = __ldg(src + eBase + lane);
        myD = __ldg(dst + eBase + lane);
        myW = __ldg(ew  + eBase + lane);
    }

    #pragma unroll
    for (int it = 0; it < 8; it++) {
        int   k = it * 2 + sub;
        int   s = __shfl_sync(0xffffffffu, myS, k);
        float w = __shfl_sync(0xffffffffu, myW, k);
        float4 v = __ldg(h + (size_t)s * 16 + l16);
        v.x *= w; v.y *= w; v.z *= w; v.w *= w;
        buf[warp][k][l16] = v;
    }
    __syncwarp();
    asm volatile("fence.proxy.async.shared::cta;" ::: "memory");

    if (lane < 16) {
        uint32_t sp = (uint32_t)__cvta_generic_to_shared(&buf[warp][lane][0]);
        float* gp = agg + (size_t)myD * 64;
        asm volatile(
            "cp.reduce.async.bulk.global.shared::cta.bulk_group.add.f32 "
            "[%0], [%1], %2;"
            :: "l"(gp), "r"(sp), "n"(256) : "memory");
        asm volatile("cp.async.bulk.commit_group;" ::: "memory");
        asm volatile("cp.async.bulk.wait_group 0;" ::: "memory");
    }
}

// ---------------------------------------------------------------------------
// Tensor-core dual GEMM, bf16-split, fp32 accum. PDL-aware.
// __launch_bounds__(256,3): cap regs ~84 -> 3 CTAs/SM -> 391 blocks in ONE
// wave (was RF-limited to 2 CTAs/SM = 2 waves = the observed 15.5us).
// ---------------------------------------------------------------------------
__device__ __forceinline__ void ldsm_x4(uint32_t& r0, uint32_t& r1,
                                        uint32_t& r2, uint32_t& r3,
                                        uint32_t addr) {
    asm volatile("ldmatrix.sync.aligned.m8n8.x4.shared.b16 {%0,%1,%2,%3}, [%4];"
                 : "=r"(r0), "=r"(r1), "=r"(r2), "=r"(r3) : "r"(addr));
}

__device__ __forceinline__ void mma_bf16(float* d, const uint32_t* a,
                                         uint32_t b0, uint32_t b1) {
    asm volatile(
        "mma.sync.aligned.m16n8k16.row.col.f32.bf16.bf16.f32 "
        "{%0,%1,%2,%3}, {%4,%5,%6,%7}, {%8,%9}, {%0,%1,%2,%3};"
        : "+f"(d[0]), "+f"(d[1]), "+f"(d[2]), "+f"(d[3])
        : "r"(a[0]), "r"(a[1]), "r"(a[2]), "r"(a[3]), "r"(b0), "r"(b1));
}

__device__ __forceinline__ void split2(float a, float b,
                                       __nv_bfloat162& h, __nv_bfloat162& l) {
    __nv_bfloat16 ha = __float2bfloat16_rn(a);
    __nv_bfloat16 hb = __float2bfloat16_rn(b);
    float la = a - __bfloat162float(ha);
    float lb = b - __bfloat162float(hb);
    h = __halves2bfloat162(ha, hb);
    l = __halves2bfloat162(__float2bfloat16_rn(la), __float2bfloat16_rn(lb));
}

__global__ __launch_bounds__(256, 3) void gemm_tc_kernel(
    const float* __restrict__ H,
    float*                    AGG,     // no restrict: loaded then zeroed
    const float* __restrict__ Wroot,   // [64][64]
    const float* __restrict__ Wrel,    // [64][64]
    const float* __restrict__ bias,    // [64]
    float*       __restrict__ out,
    int doTanh, int doZero)
{
    extern __shared__ __nv_bfloat16 sm[];
    uint32_t sbase;
    asm("{.reg .u64 t; cvta.to.shared.u64 t, %1; cvt.u32.u64 %0, t;}"
        : "=r"(sbase) : "l"(sm));

    const int tid     = threadIdx.x;
    const int lane    = tid & 31;
    const int warp    = tid >> 5;
    const int wm      = warp >> 1;
    const int wn      = warp & 1;
    const int rowBase = blockIdx.x * 128;

    float acc[2][4][4];
    #pragma unroll
    for (int mi = 0; mi < 2; mi++)
        #pragma unroll
        for (int ni = 0; ni < 4; ni++)
            #pragma unroll
            for (int k = 0; k < 4; k++) acc[mi][ni][k] = 0.f;

    const int m0 = wm * 32;
    const int n0 = wn * 32;
    const int aRow  = m0 + (lane & 15);
    const int aColB = (lane >> 4) * 8;
    const int bRow  = n0 + (lane & 7) + ((lane >> 4) * 8);
    const int bColB = ((lane >> 3) & 1) * 8;

    #pragma unroll 1
    for (int s = 0; s < 2; s++) {
        __syncthreads();

        // Gate only the scatter-dependent stage.
        if (s == 1) cudaGridDependencySynchronize();

        const float* S = s ? (const float*)AGG : H;
        #pragma unroll
        for (int i = 0; i < 8; i++) {
            int q   = tid + i * 256;
            int row = q >> 4;
            int c4  = (q & 15) * 4;
            int gr  = rowBase + row;
            float4 v = make_float4(0.f, 0.f, 0.f, 0.f);
            if (gr < N_NODES) v = *(const float4*)(S + (size_t)gr * 64 + c4);
            __nv_bfloat162 h0, l0, h1, l1;
            split2(v.x, v.y, h0, l0);
            split2(v.z, v.w, h1, l1);
            int base = row * RA + c4;
            *(__nv_bfloat162*)&sm[OFF_A_HI + base]     = h0;
            *(__nv_bfloat162*)&sm[OFF_A_HI + base + 2] = h1;
            *(__nv_bfloat162*)&sm[OFF_A_LO + base]     = l0;
            *(__nv_bfloat162*)&sm[OFF_A_LO + base + 2] = l1;
            if (s == 1 && doZero && gr < N_NODES)
                *(float4*)(AGG + (size_t)gr * 64 + c4) =
                    make_float4(0.f, 0.f, 0.f, 0.f);
        }

        const float* Wm = s ? Wrel : Wroot;
        #pragma unroll
        for (int i = 0; i < 16; i++) {
            int q = tid + i * 256;
            int k = q >> 6;
            int n = q & 63;
            float w = __ldg(Wm + k * 64 + n);
            __nv_bfloat16 hw = __float2bfloat16_rn(w);
            float lw = w - __bfloat162float(hw);
            sm[OFF_B_HI + n * RB + k] = hw;
            sm[OFF_B_LO + n * RB + k] = __float2bfloat16_rn(lw);
        }
        __syncthreads();

        const int aOffC[3] = { OFF_A_HI, OFF_A_HI, OFF_A_LO };
        const int bOffC[3] = { OFF_B_HI, OFF_B_LO, OFF_B_HI };
        #pragma unroll
        for (int c = 0; c < 3; c++) {
            uint32_t aBase = sbase + (uint32_t)(aOffC[c] + aRow * RA + aColB) * 2;
            uint32_t bBase = sbase + (uint32_t)(bOffC[c] + bRow * RB + bColB) * 2;
            #pragma unroll
            for (int ks = 0; ks < 4; ks++) {
                uint32_t a[2][4], b[2][4];
                #pragma unroll
                for (int mi = 0; mi < 2; mi++)
                    ldsm_x4(a[mi][0], a[mi][1], a[mi][2], a[mi][3],
                            aBase + (uint32_t)(mi * 16 * RA + ks * 16) * 2);
                #pragma unroll
                for (int nb = 0; nb < 2; nb++)
                    ldsm_x4(b[nb][0], b[nb][1], b[nb][2], b[nb][3],
                            bBase + (uint32_t)(nb * 16 * RB + ks * 16) * 2);
                #pragma unroll
                for (int mi = 0; mi < 2; mi++)
                    #pragma unroll
                    for (int ni = 0; ni < 4; ni++)
                        mma_bf16(acc[mi][ni], a[mi],
                                 b[ni >> 1][(ni & 1) * 2],
                                 b[ni >> 1][(ni & 1) * 2 + 1]);
            }
        }
    }

    #pragma unroll
    for (int mi = 0; mi < 2; mi++) {
        #pragma unroll
        for (int ni = 0; ni < 4; ni++) {
            int col = n0 + ni * 8 + (lane & 3) * 2;
            float b0 = __ldg(bias + col);
            float b1 = __ldg(bias + col + 1);
            int r0 = rowBase + m0 + mi * 16 + (lane >> 2);
            #pragma unroll
            for (int h = 0; h < 2; h++) {
                int r = r0 + h * 8;
                if (r >= N_NODES) continue;
                float v0 = acc[mi][ni][h * 2]     + b0;
                float v1 = acc[mi][ni][h * 2 + 1] + b1;
                if (doTanh) {
                    asm("tanh.approx.f32 %0, %0;" : "+f"(v0));
                    asm("tanh.approx.f32 %0, %0;" : "+f"(v1));
                }
                *(float2*)(out + (size_t)r * 64 + col) = make_float2(v0, v1);
            }
        }
    }
}

// ---------------------------------------------------------------------------
// Launcher
// ---------------------------------------------------------------------------
extern "C" void kernel_launch(void* const* d_in, const int* in_sizes, int n_in,
                              void* d_out, int out_size)
{
    const float* x      = (const float*)d_in[0];
    const int*   eidx   = (const int*)  d_in[1];
    const float* ew     = (const float*)d_in[2];
    const float* W_rel  = (const float*)d_in[3];
    const float* b_rel  = (const float*)d_in[4];
    const float* W_root = (const float*)d_in[5];
    float* out = (float*)d_out;

    const int* src = eidx;
    const int* dst = eidx + N_EDGES;

    float *pA, *pB, *pAgg;
    cudaGetSymbolAddress((void**)&pA,   g_bufA);
    cudaGetSymbolAddress((void**)&pB,   g_bufB);
    cudaGetSymbolAddress((void**)&pAgg, g_agg);

    static bool attrSet = false;
    if (!attrSet) {
        cudaFuncSetAttribute(gemm_tc_kernel,
                             cudaFuncAttributeMaxDynamicSharedMemorySize,
                             SMEM_BYTES);
        attrSet = true;
    }

    const int n4 = N_NODES * (DIM / 4);
    const int zeroBlocks    = (n4 + 255) / 256;
    const int scatterBlocks = N_EDGES / (4 * 16);      // 12500
    const int gemmBlocks    = (N_NODES + 127) / 128;   // 391

    // Launch order: dummy, zero, (s,g)x3 -> ncu (-s5 -c1) profiles gemm L2.
    dummy_kernel<<<1, 32>>>();
    zero_kernel<<<zeroBlocks, 256>>>((float4*)pAgg, n4);

    const float* hprev = x;
    for (int layer = 0; layer < NLAYERS; layer++) {
        float* hnext = (layer == NLAYERS - 1) ? out : ((layer == 0) ? pA : pB);

        scatter_tma_kernel<<<scatterBlocks, 128>>>(
            (const float4*)hprev, src, dst, ew, pAgg);

        // GEMM as PDL secondary: stage 0 overlaps the scatter tail.
        {
            cudaLaunchConfig_t cfg = {};
            cfg.gridDim  = dim3(gemmBlocks);
            cfg.blockDim = dim3(256);
            cfg.dynamicSmemBytes = SMEM_BYTES;
            cfg.stream = 0;
            cudaLaunchAttribute at[1];
            at[0].id = cudaLaunchAttributeProgrammaticStreamSerialization;
            at[0].val.programmaticStreamSerializationAllowed = 1;
            cfg.attrs = at;
            cfg.numAttrs = 1;

            const float* Wr = W_root + (size_t)layer * DIM * DIM;
            const float* We = W_rel  + (size_t)layer * DIM * DIM;
            const float* bs = b_rel  + (size_t)layer * DIM;
            int doTanh = (layer == NLAYERS - 1) ? 1 : 0;
            int doZero = (layer == NLAYERS - 1) ? 0 : 1;
            cudaLaunchKernelEx(&cfg, gemm_tc_kernel,
                               hprev, pAgg, Wr, We, bs, hnext, doTanh, doZero);
        }

        hprev = hnext;
    }
}

// round 11
// speedup vs baseline: 1.0719x; 1.0154x over previous
#include <cuda_runtime.h>
#include <cuda_bf16.h>
#include <cstdint>

#define N_NODES 50000
#define N_EDGES 800000
#define DIM     64
#define NLAYERS 3

// A/B row strides in bf16 elems (64 data + 8 pad -> conflict-free LDSM)
#define RA 72
#define RB 72
#define OFF_A_HI 0
#define OFF_A_LO (128 * RA)
#define OFF_B_HI (2 * 128 * RA)
#define OFF_B_LO (2 * 128 * RA + 64 * RB)
#define SMEM_ELEMS (2 * 128 * RA + 2 * 64 * RB)
#define SMEM_BYTES (SMEM_ELEMS * 2)

// Scratch (no cudaMalloc allowed).
__device__ float g_bufA[N_NODES * DIM];
__device__ float g_bufB[N_NODES * DIM];
__device__ float g_agg [N_NODES * DIM];

// ---------------------------------------------------------------------------
// Zero agg (once, before layer-1 scatter; later layers zeroed inside GEMM)
// ---------------------------------------------------------------------------
__global__ void zero_kernel(float4* __restrict__ p, int n4) {
    int i = blockIdx.x * blockDim.x + threadIdx.x;
    if (i < n4) p[i] = make_float4(0.f, 0.f, 0.f, 0.f);
}

// ---------------------------------------------------------------------------
// HYBRID scatter: agg[dst] += ew * h[src], 16 edges per warp.
//   edges 0..7  -> SMEM staging + cp.reduce.async.bulk (TMA engine path)
//   edges 8..15 -> red.global.add.v4.f32 from registers (LSU path, no SMEM)
// The two paths use disjoint SM-side resources (L1TEX staging+TMA vs LSU
// issue), halving pressure on each; they share only gather LDGs and the
// L2-side atomic ALU.
// ---------------------------------------------------------------------------
__global__ __launch_bounds__(128) void scatter_hybrid_kernel(
    const float4* __restrict__ h,
    const int*    __restrict__ src,
    const int*    __restrict__ dst,
    const float*  __restrict__ ew,
    float*        __restrict__ agg)
{
    __shared__ float4 buf[4][8][16];   // [warp][edge0..7][lane16] = 8KB

    const int warp = threadIdx.x >> 5;
    const int lane = threadIdx.x & 31;
    const int sub  = lane >> 4;            // which edge of the pair
    const int l16  = lane & 15;

    const long eBase = ((long)blockIdx.x * 4 + warp) * 16;

    // Coalesced key loads: lane i (i<16) owns edge eBase+i.
    int   myS = 0, myD = 0;
    float myW = 0.f;
    if (lane < 16) {
        myS = __ldg(src + eBase + lane);
        myD = __ldg(dst + eBase + lane);
        myW = __ldg(ew  + eBase + lane);
    }

    // ---- Path A: edges 0..7 staged into SMEM for bulk reduce ----
    #pragma unroll
    for (int it = 0; it < 4; it++) {
        int   k = it * 2 + sub;
        int   s = __shfl_sync(0xffffffffu, myS, k);
        float w = __shfl_sync(0xffffffffu, myW, k);
        float4 v = __ldg(h + (size_t)s * 16 + l16);
        v.x *= w; v.y *= w; v.z *= w; v.w *= w;
        buf[warp][k][l16] = v;
    }
    __syncwarp();
    asm volatile("fence.proxy.async.shared::cta;" ::: "memory");

    // Issue bulk reduces early so the TMA engine works while we do path B.
    if (lane < 8) {
        uint32_t sp = (uint32_t)__cvta_generic_to_shared(&buf[warp][lane][0]);
        float* gp = agg + (size_t)myD * 64;
        asm volatile(
            "cp.reduce.async.bulk.global.shared::cta.bulk_group.add.f32 "
            "[%0], [%1], %2;"
            :: "l"(gp), "r"(sp), "n"(256) : "memory");
        asm volatile("cp.async.bulk.commit_group;" ::: "memory");
    }

    // ---- Path B: edges 8..15 via direct vector REDG (no SMEM) ----
    #pragma unroll
    for (int it = 0; it < 4; it++) {
        int   k = 8 + it * 2 + sub;
        int   s = __shfl_sync(0xffffffffu, myS, k);
        int   d = __shfl_sync(0xffffffffu, myD, k);
        float w = __shfl_sync(0xffffffffu, myW, k);
        float4 v = __ldg(h + (size_t)s * 16 + l16);
        float4* p = (float4*)agg + (size_t)d * 16 + l16;
        asm volatile("red.global.add.v4.f32 [%0], {%1,%2,%3,%4};"
                     :: "l"(p), "f"(v.x * w), "f"(v.y * w),
                        "f"(v.z * w), "f"(v.w * w)
                     : "memory");
    }

    if (lane < 8)
        asm volatile("cp.async.bulk.wait_group 0;" ::: "memory");
}

// ---------------------------------------------------------------------------
// Tensor-core dual GEMM, bf16-split, fp32 accum. PDL-aware (unchanged).
// ---------------------------------------------------------------------------
__device__ __forceinline__ void ldsm_x4(uint32_t& r0, uint32_t& r1,
                                        uint32_t& r2, uint32_t& r3,
                                        uint32_t addr) {
    asm volatile("ldmatrix.sync.aligned.m8n8.x4.shared.b16 {%0,%1,%2,%3}, [%4];"
                 : "=r"(r0), "=r"(r1), "=r"(r2), "=r"(r3) : "r"(addr));
}

__device__ __forceinline__ void mma_bf16(float* d, const uint32_t* a,
                                         uint32_t b0, uint32_t b1) {
    asm volatile(
        "mma.sync.aligned.m16n8k16.row.col.f32.bf16.bf16.f32 "
        "{%0,%1,%2,%3}, {%4,%5,%6,%7}, {%8,%9}, {%0,%1,%2,%3};"
        : "+f"(d[0]), "+f"(d[1]), "+f"(d[2]), "+f"(d[3])
        : "r"(a[0]), "r"(a[1]), "r"(a[2]), "r"(a[3]), "r"(b0), "r"(b1));
}

__device__ __forceinline__ void split2(float a, float b,
                                       __nv_bfloat162& h, __nv_bfloat162& l) {
    __nv_bfloat16 ha = __float2bfloat16_rn(a);
    __nv_bfloat16 hb = __float2bfloat16_rn(b);
    float la = a - __bfloat162float(ha);
    float lb = b - __bfloat162float(hb);
    h = __halves2bfloat162(ha, hb);
    l = __halves2bfloat162(__float2bfloat16_rn(la), __float2bfloat16_rn(lb));
}

__global__ __launch_bounds__(256, 3) void gemm_tc_kernel(
    const float* __restrict__ H,
    float*                    AGG,     // no restrict: loaded then zeroed
    const float* __restrict__ Wroot,   // [64][64]
    const float* __restrict__ Wrel,    // [64][64]
    const float* __restrict__ bias,    // [64]
    float*       __restrict__ out,
    int doTanh, int doZero)
{
    extern __shared__ __nv_bfloat16 sm[];
    uint32_t sbase;
    asm("{.reg .u64 t; cvta.to.shared.u64 t, %1; cvt.u32.u64 %0, t;}"
        : "=r"(sbase) : "l"(sm));

    const int tid     = threadIdx.x;
    const int lane    = tid & 31;
    const int warp    = tid >> 5;
    const int wm      = warp >> 1;
    const int wn      = warp & 1;
    const int rowBase = blockIdx.x * 128;

    float acc[2][4][4];
    #pragma unroll
    for (int mi = 0; mi < 2; mi++)
        #pragma unroll
        for (int ni = 0; ni < 4; ni++)
            #pragma unroll
            for (int k = 0; k < 4; k++) acc[mi][ni][k] = 0.f;

    const int m0 = wm * 32;
    const int n0 = wn * 32;
    const int aRow  = m0 + (lane & 15);
    const int aColB = (lane >> 4) * 8;
    const int bRow  = n0 + (lane & 7) + ((lane >> 4) * 8);
    const int bColB = ((lane >> 3) & 1) * 8;

    #pragma unroll 1
    for (int s = 0; s < 2; s++) {
        __syncthreads();

        // Gate only the scatter-dependent stage.
        if (s == 1) cudaGridDependencySynchronize();

        const float* S = s ? (const float*)AGG : H;
        #pragma unroll
        for (int i = 0; i < 8; i++) {
            int q   = tid + i * 256;
            int row = q >> 4;
            int c4  = (q & 15) * 4;
            int gr  = rowBase + row;
            float4 v = make_float4(0.f, 0.f, 0.f, 0.f);
            if (gr < N_NODES) v = *(const float4*)(S + (size_t)gr * 64 + c4);
            __nv_bfloat162 h0, l0, h1, l1;
            split2(v.x, v.y, h0, l0);
            split2(v.z, v.w, h1, l1);
            int base = row * RA + c4;
            *(__nv_bfloat162*)&sm[OFF_A_HI + base]     = h0;
            *(__nv_bfloat162*)&sm[OFF_A_HI + base + 2] = h1;
            *(__nv_bfloat162*)&sm[OFF_A_LO + base]     = l0;
            *(__nv_bfloat162*)&sm[OFF_A_LO + base + 2] = l1;
            if (s == 1 && doZero && gr < N_NODES)
                *(float4*)(AGG + (size_t)gr * 64 + c4) =
                    make_float4(0.f, 0.f, 0.f, 0.f);
        }

        const float* Wm = s ? Wrel : Wroot;
        #pragma unroll
        for (int i = 0; i < 16; i++) {
            int q = tid + i * 256;
            int k = q >> 6;
            int n = q & 63;
            float w = __ldg(Wm + k * 64 + n);
            __nv_bfloat16 hw = __float2bfloat16_rn(w);
            float lw = w - __bfloat162float(hw);
            sm[OFF_B_HI + n * RB + k] = hw;
            sm[OFF_B_LO + n * RB + k] = __float2bfloat16_rn(lw);
        }
        __syncthreads();

        const int aOffC[3] = { OFF_A_HI, OFF_A_HI, OFF_A_LO };
        const int bOffC[3] = { OFF_B_HI, OFF_B_LO, OFF_B_HI };
        #pragma unroll
        for (int c = 0; c < 3; c++) {
            uint32_t aBase = sbase + (uint32_t)(aOffC[c] + aRow * RA + aColB) * 2;
            uint32_t bBase = sbase + (uint32_t)(bOffC[c] + bRow * RB + bColB) * 2;
            #pragma unroll
            for (int ks = 0; ks < 4; ks++) {
                uint32_t a[2][4], b[2][4];
                #pragma unroll
                for (int mi = 0; mi < 2; mi++)
                    ldsm_x4(a[mi][0], a[mi][1], a[mi][2], a[mi][3],
                            aBase + (uint32_t)(mi * 16 * RA + ks * 16) * 2);
                #pragma unroll
                for (int nb = 0; nb < 2; nb++)
                    ldsm_x4(b[nb][0], b[nb][1], b[nb][2], b[nb][3],
                            bBase + (uint32_t)(nb * 16 * RB + ks * 16) * 2);
                #pragma unroll
                for (int mi = 0; mi < 2; mi++)
                    #pragma unroll
                    for (int ni = 0; ni < 4; ni++)
                        mma_bf16(acc[mi][ni], a[mi],
                                 b[ni >> 1][(ni & 1) * 2],
                                 b[ni >> 1][(ni & 1) * 2 + 1]);
            }
        }
    }

    #pragma unroll
    for (int mi = 0; mi < 2; mi++) {
        #pragma unroll
        for (int ni = 0; ni < 4; ni++) {
            int col = n0 + ni * 8 + (lane & 3) * 2;
            float b0 = __ldg(bias + col);
            float b1 = __ldg(bias + col + 1);
            int r0 = rowBase + m0 + mi * 16 + (lane >> 2);
            #pragma unroll
            for (int h = 0; h < 2; h++) {
                int r = r0 + h * 8;
                if (r >= N_NODES) continue;
                float v0 = acc[mi][ni][h * 2]     + b0;
                float v1 = acc[mi][ni][h * 2 + 1] + b1;
                if (doTanh) {
                    asm("tanh.approx.f32 %0, %0;" : "+f"(v0));
                    asm("tanh.approx.f32 %0, %0;" : "+f"(v1));
                }
                *(float2*)(out + (size_t)r * 64 + col) = make_float2(v0, v1);
            }
        }
    }
}

// ---------------------------------------------------------------------------
// Launcher
// ---------------------------------------------------------------------------
extern "C" void kernel_launch(void* const* d_in, const int* in_sizes, int n_in,
                              void* d_out, int out_size)
{
    const float* x      = (const float*)d_in[0];
    const int*   eidx   = (const int*)  d_in[1];
    const float* ew     = (const float*)d_in[2];
    const float* W_rel  = (const float*)d_in[3];
    const float* b_rel  = (const float*)d_in[4];
    const float* W_root = (const float*)d_in[5];
    float* out = (float*)d_out;

    const int* src = eidx;
    const int* dst = eidx + N_EDGES;

    float *pA, *pB, *pAgg;
    cudaGetSymbolAddress((void**)&pA,   g_bufA);
    cudaGetSymbolAddress((void**)&pB,   g_bufB);
    cudaGetSymbolAddress((void**)&pAgg, g_agg);

    static bool attrSet = false;
    if (!attrSet) {
        cudaFuncSetAttribute(gemm_tc_kernel,
                             cudaFuncAttributeMaxDynamicSharedMemorySize,
                             SMEM_BYTES);
        attrSet = true;
    }

    const int n4 = N_NODES * (DIM / 4);
    const int zeroBlocks    = (n4 + 255) / 256;
    const int scatterBlocks = N_EDGES / (4 * 16);      // 12500
    const int gemmBlocks    = (N_NODES + 127) / 128;   // 391

    // Launch order: zero, (scatter, gemm) x3 -> launch #6 = layer-3 scatter
    zero_kernel<<<zeroBlocks, 256>>>((float4*)pAgg, n4);

    const float* hprev = x;
    for (int layer = 0; layer < NLAYERS; layer++) {
        float* hnext = (layer == NLAYERS - 1) ? out : ((layer == 0) ? pA : pB);

        scatter_hybrid_kernel<<<scatterBlocks, 128>>>(
            (const float4*)hprev, src, dst, ew, pAgg);

        // GEMM as PDL secondary: stage 0 overlaps the scatter tail.
        {
            cudaLaunchConfig_t cfg = {};
            cfg.gridDim  = dim3(gemmBlocks);
            cfg.blockDim = dim3(256);
            cfg.dynamicSmemBytes = SMEM_BYTES;
            cfg.stream = 0;
            cudaLaunchAttribute at[1];
            at[0].id = cudaLaunchAttributeProgrammaticStreamSerialization;
            at[0].val.programmaticStreamSerializationAllowed = 1;
            cfg.attrs = at;
            cfg.numAttrs = 1;

            const float* Wr = W_root + (size_t)layer * DIM * DIM;
            const float* We = W_rel  + (size_t)layer * DIM * DIM;
            const float* bs = b_rel  + (size_t)layer * DIM;
            int doTanh = (layer == NLAYERS - 1) ? 1 : 0;
            int doZero = (layer == NLAYERS - 1) ? 0 : 1;
            cudaLaunchKernelEx(&cfg, gemm_tc_kernel,
                               hprev, pAgg, Wr, We, bs, hnext, doTanh, doZero);
        }

        hprev = hnext;
    }
}